// round 10
// baseline (speedup 1.0000x reference)
#include <cuda_runtime.h>
#include <cuda_bf16.h>
#include <math.h>
#include <stdint.h>
#include <string.h>

// Problem constants
#define SEQ    128
#define BATCH  32
#define NTOKEN 32000
#define NINP   1024
#define NHID   1024
#define MROWS  (SEQ * BATCH)          // 4096

// ---------------- scratch (no runtime allocation allowed) ----------------
__device__ float g_xin[MROWS * NHID];        // 16 MB
__device__ float g_hs [MROWS * NHID];        // 16 MB (fp32, scan-internal)
__device__ float g_t32buf[MROWS * NHID];     // 16 MB (tf32 bits: emb32 then hs32)
__device__ float g_decW_t32[NTOKEN * NHID];  // 131 MB (tf32 bits)
__device__ float g_wih_t32[NHID * NINP];     // 4 MB (tf32 bits)
__device__ unsigned g_flags[128];            // scan barrier flags (one per CTA)

// ---------------- helpers ----------------
__device__ __forceinline__ uint32_t smem_u32(const void* p) {
    return (uint32_t)__cvta_generic_to_shared(p);
}
__device__ __forceinline__ uint32_t f2tf32(float x) {
    uint32_t r;
    asm("cvt.rna.tf32.f32 %0, %1;" : "=r"(r) : "f"(x));
    return r;
}

#define LDSM_X4(r0, r1, r2, r3, addr) \
    asm volatile("ldmatrix.sync.aligned.m8n8.x4.shared.b16 {%0,%1,%2,%3}, [%4];" \
        : "=r"(r0), "=r"(r1), "=r"(r2), "=r"(r3) : "r"(addr))

#define FMA_X2(acc, a, b) \
    asm volatile("fma.rn.f32x2 %0, %1, %2, %0;" : "+l"(acc) : "l"(a), "l"(b))

// =============== prep_a: dec_W -> tf32 (the big conversion) =============
__global__ __launch_bounds__(256)
void prep_a_kernel(const float* __restrict__ dec_W)
{
    const long n4 = (long)NTOKEN * NHID / 4;
    long i = (long)blockIdx.x * 256 + threadIdx.x;
    const long stride = (long)gridDim.x * 256;
    for (; i < n4; i += stride) {
        float4 v = ((const float4*)dec_W)[i];
        uint4 o = { f2tf32(v.x), f2tf32(v.y), f2tf32(v.z), f2tf32(v.w) };
        ((uint4*)g_decW_t32)[i] = o;
    }
}

// =============== prep_b: W_ih cvt + emb gather + flag reset =============
#define PREP_B_BLOCKS 192

__global__ __launch_bounds__(256)
void prep_b_kernel(const float* __restrict__ W_ih,
                   const float* __restrict__ emb_W,
                   const int*   __restrict__ input)
{
    const int bid = blockIdx.x;
    const int t   = threadIdx.x;
    if (bid == 0 && t < 128) g_flags[t] = 0u;

    if (bid < 64) {
        const long n4 = (long)NHID * NINP / 4;
        long i = (long)bid * 256 + t;
        const long stride = 64L * 256;
        for (; i < n4; i += stride) {
            float4 v = ((const float4*)W_ih)[i];
            uint4 o = { f2tf32(v.x), f2tf32(v.y), f2tf32(v.z), f2tf32(v.w) };
            ((uint4*)g_wih_t32)[i] = o;
        }
    } else {
        const long n4 = (long)MROWS * NINP / 4;
        long i = (long)(bid - 64) * 256 + t;
        const long stride = 128L * 256;
        for (; i < n4; i += stride) {
            int row = (int)(i >> 8);          // NINP/4 = 256 float4 per row
            int c4  = (int)(i & 255);
            int tok = input[row];
            float4 v = *(const float4*)(emb_W + (long)tok * NINP + c4 * 4);
            uint4 o = { f2tf32(v.x), f2tf32(v.y), f2tf32(v.z), f2tf32(v.w) };
            *(uint4*)(g_t32buf + (long)row * NINP + c4 * 4) = o;
        }
    }
}

// ============ tf32 mma.sync GEMM with ldmatrix fragments ============
// C[M,N] = A[M,K]*B[N,K]^T + bias. CTA tile 128x128x32, 4 warps (64x64 each),
// 128 threads, 2 CTAs/SM. Swizzled 128B smem rows, 3 buffers, 2 groups in
// flight, ONE __syncthreads per chunk.
#define DBM 128
#define DBN 128
#define DBK 32
#define NSTG 3
#define NTHR 128
#define A_ST (DBM * DBK * 4)   // 16 KB
#define B_ST (DBN * DBK * 4)   // 16 KB
#define DEC_SMEM (NSTG * (A_ST + B_ST))   // 96 KB

__global__ __launch_bounds__(NTHR, 2)
void gemm_tf32_ldsm(const float* __restrict__ A,
                    const float* __restrict__ B,
                    const float* __restrict__ bias,
                    float*       __restrict__ C,
                    int M, int N, int K)
{
    extern __shared__ __align__(1024) char smem[];
    const uint32_t sA = smem_u32(smem);
    const uint32_t sB = sA + NSTG * A_ST;

    const int t    = threadIdx.x;
    const int warp = t >> 5;
    const int lane = t & 31;
    const int m0   = blockIdx.x * DBM;
    const int n0   = blockIdx.y * DBN;
    const int wm   = warp & 1;
    const int wn   = warp >> 1;
    const int g    = lane >> 2;
    const int tg   = lane & 3;

    const int mat = lane >> 3;
    const int sub = lane & 7;

    uint32_t aRowOff[4], aSw[4];
#pragma unroll
    for (int mi = 0; mi < 4; ++mi) {
        int r = wm * 64 + mi * 16 + (mat & 1) * 8 + sub;
        aRowOff[mi] = (uint32_t)(r * 128);
        aSw[mi]     = (uint32_t)(r & 7);
    }
    const uint32_t aMatK = (uint32_t)(mat >> 1);

    uint32_t bRowOff[4], bSw[4];
#pragma unroll
    for (int p = 0; p < 4; ++p) {
        int r = wn * 64 + (p * 2 + (mat >> 1)) * 8 + sub;
        bRowOff[p] = (uint32_t)(r * 128);
        bSw[p]     = (uint32_t)(r & 7);
    }
    const uint32_t bMatK = (uint32_t)(mat & 1);

    float acc[4][8][4];
#pragma unroll
    for (int mi = 0; mi < 4; ++mi)
#pragma unroll
        for (int ni = 0; ni < 8; ++ni)
#pragma unroll
            for (int r = 0; r < 4; ++r) acc[mi][ni][r] = 0.0f;

    auto load_chunk = [&](int c) {
        const int s  = c % NSTG;
        const int k0 = c * DBK;
#pragma unroll
        for (int i = 0; i < 8; ++i) {
            int id  = t + i * NTHR;
            int row = id >> 3;
            int kc  = id & 7;
            uint32_t sw = (uint32_t)(row * 128 + ((kc ^ (row & 7)) << 4));
            uint32_t dst = sA + s * A_ST + sw;
            const float* ga = A + (long)(m0 + row) * K + k0 + kc * 4;
            asm volatile("cp.async.cg.shared.global [%0], [%1], 16;" :: "r"(dst), "l"(ga));
        }
#pragma unroll
        for (int i = 0; i < 8; ++i) {
            int id  = t + i * NTHR;
            int row = id >> 3;
            int kc  = id & 7;
            uint32_t sw = (uint32_t)(row * 128 + ((kc ^ (row & 7)) << 4));
            uint32_t dst = sB + s * B_ST + sw;
            const float* gb = B + (long)(n0 + row) * K + k0 + kc * 4;
            asm volatile("cp.async.cg.shared.global [%0], [%1], 16;" :: "r"(dst), "l"(gb));
        }
        asm volatile("cp.async.commit_group;");
    };

    const int NCHUNK = K / DBK;   // 32
    load_chunk(0);
    load_chunk(1);

    for (int c = 0; c < NCHUNK; ++c) {
        const int buf = c % NSTG;
        asm volatile("cp.async.wait_group 1;");
        __syncthreads();

        if (c + 2 < NCHUNK) {
            load_chunk(c + 2);
        } else {
            asm volatile("cp.async.commit_group;");
        }

        const uint32_t Ab = sA + buf * A_ST;
        const uint32_t Bb = sB + buf * B_ST;

#pragma unroll
        for (int kk = 0; kk < 4; ++kk) {
            uint32_t a[4][4];
            uint32_t b[8][2];
            const uint32_t cA = (uint32_t)(kk * 2) + aMatK;
            const uint32_t cB = (uint32_t)(kk * 2) + bMatK;
#pragma unroll
            for (int mi = 0; mi < 4; ++mi) {
                uint32_t addr = Ab + aRowOff[mi] + (((cA ^ aSw[mi])) << 4);
                LDSM_X4(a[mi][0], a[mi][1], a[mi][2], a[mi][3], addr);
            }
#pragma unroll
            for (int p = 0; p < 4; ++p) {
                uint32_t addr = Bb + bRowOff[p] + (((cB ^ bSw[p])) << 4);
                uint32_t r0, r1, r2, r3;
                LDSM_X4(r0, r1, r2, r3, addr);
                b[2 * p][0] = r0;     b[2 * p][1] = r1;
                b[2 * p + 1][0] = r2; b[2 * p + 1][1] = r3;
            }
#pragma unroll
            for (int mi = 0; mi < 4; ++mi)
#pragma unroll
                for (int ni = 0; ni < 8; ++ni) {
                    asm volatile(
                        "mma.sync.aligned.m16n8k8.row.col.f32.tf32.tf32.f32 "
                        "{%0,%1,%2,%3}, {%4,%5,%6,%7}, {%8,%9}, {%0,%1,%2,%3};\n"
                        : "+f"(acc[mi][ni][0]), "+f"(acc[mi][ni][1]),
                          "+f"(acc[mi][ni][2]), "+f"(acc[mi][ni][3])
                        : "r"(a[mi][0]), "r"(a[mi][1]), "r"(a[mi][2]), "r"(a[mi][3]),
                          "r"(b[ni][0]), "r"(b[ni][1]));
                }
        }
    }

    // ---- epilogue: add bias, store ----
#pragma unroll
    for (int mi = 0; mi < 4; ++mi) {
        int rbase = m0 + wm * 64 + mi * 16 + g;
#pragma unroll
        for (int ni = 0; ni < 8; ++ni) {
            int cc = n0 + wn * 64 + ni * 8 + 2 * tg;
            float b0 = bias[cc], b1 = bias[cc + 1];
            float2 v0 = make_float2(acc[mi][ni][0] + b0, acc[mi][ni][1] + b1);
            float2 v1 = make_float2(acc[mi][ni][2] + b0, acc[mi][ni][3] + b1);
            *(float2*)(C + (long)rbase * N + cc)       = v0;
            *(float2*)(C + (long)(rbase + 8) * N + cc) = v1;
        }
    }
}

// ---------------- persistent RNN scan ----------------
// 128 CTAs x 512 threads. Block jb owns hidden cols [jb*8, jb*8+8).
// 16-way K split (warp kg covers k in [kg*64, kg*64+64)).
// Flag-array barrier: CTA jb releases g_flags[jb] = gen (st.release.gpu, no
// atomics, zero contention); then threads 0..127 each poll one flag with
// ld.acquire.gpu. Monotonic generations; prep_b zeroes the flags per replay.
#define SCAN_NB   128
#define SCAN_THR  512

__device__ __forceinline__ void scan_barrier(int jb, unsigned gen, int t) {
    __syncthreads();   // all smem/global writes of this CTA done
    if (t == 0) {
        asm volatile("st.release.gpu.global.u32 [%0], %1;"
                     :: "l"(&g_flags[jb]), "r"(gen) : "memory");
    }
    if (t < 128) {
        unsigned r;
        do {
            asm volatile("ld.acquire.gpu.global.u32 %0, [%1];"
                         : "=r"(r) : "l"(&g_flags[t]) : "memory");
        } while (r < gen);
    }
    __syncthreads();   // propagate acquired visibility CTA-wide
}

// Writes: hs (fp32), hs32 (tf32 bits), hidden_f at s == SEQ-1.
__global__ __launch_bounds__(SCAN_THR)
void scan_kernel(const float* __restrict__ xin,
                 const float* __restrict__ h0,
                 const float* __restrict__ W_hh,
                 const float* __restrict__ b_hh,
                 const float* __restrict__ alpha,
                 float*       __restrict__ hs,
                 float*       __restrict__ hs32,
                 float*       __restrict__ hidden_f)
{
    extern __shared__ float sm[];
    float* Wsh = sm;                  // 8 * 1024  (32 KB)
    float* red = sm + 8 * 1024;       // 16 * 32 * 8 (16 KB)

    const int t  = threadIdx.x;
    const int jb = blockIdx.x;
    const int j0 = jb * 8;

    {
        const float4* src = (const float4*)(W_hh + (long)j0 * NHID);
        float4* dst = (float4*)Wsh;
        for (int i = t; i < 8 * NHID / 4; i += SCAN_THR) dst[i] = src[i];
    }
    __syncthreads();

    const int kg = t >> 5;    // 0..15 K-split group (64 cols each)
    const int b  = t & 31;    // batch lane
    const int b2  = (t >> 3) & 31;  // for final reduce (t < 256)
    const int jj2 = t & 7;
    const float bh = b_hh[j0 + jj2];

    for (int s = 0; s < SEQ; ++s) {
        const float* hprev = (s == 0) ? h0 : (hs + (long)(s - 1) * BATCH * NHID);

        // packed f32x2 partial sums over k in [kg*64, kg*64+64)
        unsigned long long accP[8];
#pragma unroll
        for (int jj = 0; jj < 8; ++jj) accP[jj] = 0ull;

        const float* hrow  = hprev + (long)b * NHID + kg * 64;
        const float* wbase = &Wsh[kg * 64];
#pragma unroll 4
        for (int k = 0; k < 64; k += 4) {
            ulonglong2 hq = *(const ulonglong2*)&hrow[k];
#pragma unroll
            for (int jj = 0; jj < 8; ++jj) {
                ulonglong2 wq = *(const ulonglong2*)&wbase[jj * NHID + k];
                FMA_X2(accP[jj], hq.x, wq.x);
                FMA_X2(accP[jj], hq.y, wq.y);
            }
        }

#pragma unroll
        for (int jj = 0; jj < 8; ++jj) {
            float2 f;
            memcpy(&f, &accP[jj], 8);
            red[(kg * 32 + b) * 8 + jj] = f.x + f.y;
        }
        __syncthreads();

        if (t < 256) {
            float sum = 0.0f;
#pragma unroll
            for (int kk = 0; kk < 16; ++kk) sum += red[(kk * 32 + b2) * 8 + jj2];
            long idx = (long)(s * BATCH + b2) * NHID + j0 + jj2;
            float val = xin[idx] + sum + bh;
            float hnew = alpha[s] * tanhf(val);
            hs[idx] = hnew;
            ((uint32_t*)hs32)[idx] = f2tf32(hnew);
            if (s == SEQ - 1) hidden_f[(long)b2 * NHID + j0 + jj2] = hnew;
        }

        scan_barrier(jb, (unsigned)(s + 1), t);
    }
}

// ---------------- launch ----------------
extern "C" void kernel_launch(void* const* d_in, const int* in_sizes, int n_in,
                              void* d_out, int out_size)
{
    const int*   input  = (const int*)  d_in[0];
    const float* hidden = (const float*)d_in[1];
    const float* emb_W  = (const float*)d_in[2];
    const float* W_ih   = (const float*)d_in[3];
    const float* W_hh   = (const float*)d_in[4];
    const float* b_ih   = (const float*)d_in[5];
    const float* b_hh   = (const float*)d_in[6];
    const float* alpha  = (const float*)d_in[7];
    const float* dec_W  = (const float*)d_in[8];
    const float* dec_b  = (const float*)d_in[9];

    float* decoded  = (float*)d_out;                          // [S,B,NTOKEN]
    float* hidden_f = (float*)d_out + (long)MROWS * NTOKEN;   // [B,NHID]

    void *xin_p, *hs_p, *t32_p, *decw32_p, *wih32_p;
    cudaGetSymbolAddress(&xin_p,    g_xin);
    cudaGetSymbolAddress(&hs_p,     g_hs);
    cudaGetSymbolAddress(&t32_p,    g_t32buf);
    cudaGetSymbolAddress(&decw32_p, g_decW_t32);
    cudaGetSymbolAddress(&wih32_p,  g_wih_t32);
    float* xin     = (float*)xin_p;
    float* hs      = (float*)hs_p;
    float* t32     = (float*)t32_p;
    float* decw32  = (float*)decw32_p;
    float* wih32   = (float*)wih32_p;

    const int scan_smem = (8 * 1024 + 16 * 32 * 8) * (int)sizeof(float);
    cudaFuncSetAttribute(scan_kernel, cudaFuncAttributeMaxDynamicSharedMemorySize, scan_smem);
    cudaFuncSetAttribute(gemm_tf32_ldsm, cudaFuncAttributeMaxDynamicSharedMemorySize, DEC_SMEM);

    // 1) prep_a: dec_W -> tf32
    prep_a_kernel<<<2048, 256>>>(dec_W);

    // 2) prep_b: W_ih cvt + emb gather + flag reset
    prep_b_kernel<<<PREP_B_BLOCKS, 256>>>(W_ih, emb_W, input);

    // 3) xin = emb @ W_ih^T + b_ih on tensor cores [4096 x 1024]
    gemm_tf32_ldsm<<<dim3(MROWS / DBM, NHID / DBN), NTHR, DEC_SMEM>>>(
        t32, wih32, b_ih, xin, MROWS, NHID, NINP);

    // 4) recurrence — 4th launch: ncu target
    scan_kernel<<<SCAN_NB, SCAN_THR, scan_smem>>>(xin, hidden, W_hh, b_hh, alpha,
                                                  hs, t32, hidden_f);

    // 5) decoder: decoded = hs @ dec_W^T + dec_b  [4096 x 32000]
    gemm_tf32_ldsm<<<dim3(MROWS / DBM, NTOKEN / DBN), NTHR, DEC_SMEM>>>(
        t32, decw32, dec_b, decoded, MROWS, NTOKEN, NHID);
}

// round 11
// speedup vs baseline: 1.3514x; 1.3514x over previous
#include <cuda_runtime.h>
#include <cuda_bf16.h>
#include <math.h>
#include <stdint.h>
#include <string.h>

// Problem constants
#define SEQ    128
#define BATCH  32
#define NTOKEN 32000
#define NINP   1024
#define NHID   1024
#define MROWS  (SEQ * BATCH)          // 4096

// ---------------- scratch (no runtime allocation allowed) ----------------
__device__ float g_xin[MROWS * NHID];        // 16 MB
__device__ float g_hs [MROWS * NHID];        // 16 MB (fp32, scan-internal)
__device__ float g_t32buf[MROWS * NHID];     // 16 MB (tf32 bits: emb32 then hs32)
__device__ float g_decW_t32[NTOKEN * NHID];  // 131 MB (tf32 bits)
__device__ float g_wih_t32[NHID * NINP];     // 4 MB (tf32 bits)
__device__ unsigned g_arr[8 * 32];           // 8 arrival counters, 128B apart

// ---------------- helpers ----------------
__device__ __forceinline__ uint32_t smem_u32(const void* p) {
    return (uint32_t)__cvta_generic_to_shared(p);
}
__device__ __forceinline__ uint32_t f2tf32(float x) {
    uint32_t r;
    asm("cvt.rna.tf32.f32 %0, %1;" : "=r"(r) : "f"(x));
    return r;
}

#define LDSM_X4(r0, r1, r2, r3, addr) \
    asm volatile("ldmatrix.sync.aligned.m8n8.x4.shared.b16 {%0,%1,%2,%3}, [%4];" \
        : "=r"(r0), "=r"(r1), "=r"(r2), "=r"(r3) : "r"(addr))

#define FMA_X2(acc, a, b) \
    asm volatile("fma.rn.f32x2 %0, %1, %2, %0;" : "+l"(acc) : "l"(a), "l"(b))

// =============== prep_a: dec_W -> tf32 (the big conversion) =============
__global__ __launch_bounds__(256)
void prep_a_kernel(const float* __restrict__ dec_W)
{
    const long n4 = (long)NTOKEN * NHID / 4;
    long i = (long)blockIdx.x * 256 + threadIdx.x;
    const long stride = (long)gridDim.x * 256;
    for (; i < n4; i += stride) {
        float4 v = ((const float4*)dec_W)[i];
        uint4 o = { f2tf32(v.x), f2tf32(v.y), f2tf32(v.z), f2tf32(v.w) };
        ((uint4*)g_decW_t32)[i] = o;
    }
}

// =============== prep_b: W_ih cvt + emb gather + counter reset =============
#define PREP_B_BLOCKS 192

__global__ __launch_bounds__(256)
void prep_b_kernel(const float* __restrict__ W_ih,
                   const float* __restrict__ emb_W,
                   const int*   __restrict__ input)
{
    const int bid = blockIdx.x;
    const int t   = threadIdx.x;
    if (bid == 0 && t < 256) g_arr[t] = 0u;

    if (bid < 64) {
        const long n4 = (long)NHID * NINP / 4;
        long i = (long)bid * 256 + t;
        const long stride = 64L * 256;
        for (; i < n4; i += stride) {
            float4 v = ((const float4*)W_ih)[i];
            uint4 o = { f2tf32(v.x), f2tf32(v.y), f2tf32(v.z), f2tf32(v.w) };
            ((uint4*)g_wih_t32)[i] = o;
        }
    } else {
        const long n4 = (long)MROWS * NINP / 4;
        long i = (long)(bid - 64) * 256 + t;
        const long stride = 128L * 256;
        for (; i < n4; i += stride) {
            int row = (int)(i >> 8);          // NINP/4 = 256 float4 per row
            int c4  = (int)(i & 255);
            int tok = input[row];
            float4 v = *(const float4*)(emb_W + (long)tok * NINP + c4 * 4);
            uint4 o = { f2tf32(v.x), f2tf32(v.y), f2tf32(v.z), f2tf32(v.w) };
            *(uint4*)(g_t32buf + (long)row * NINP + c4 * 4) = o;
        }
    }
}

// ============ tf32 mma.sync GEMM with ldmatrix fragments (R9 config) ========
#define DBM 128
#define DBN 128
#define DBK 32
#define NSTG 3
#define NTHR 128
#define A_ST (DBM * DBK * 4)   // 16 KB
#define B_ST (DBN * DBK * 4)   // 16 KB
#define DEC_SMEM (NSTG * (A_ST + B_ST))   // 96 KB

__global__ __launch_bounds__(NTHR, 2)
void gemm_tf32_ldsm(const float* __restrict__ A,
                    const float* __restrict__ B,
                    const float* __restrict__ bias,
                    float*       __restrict__ C,
                    int M, int N, int K)
{
    extern __shared__ __align__(1024) char smem[];
    const uint32_t sA = smem_u32(smem);
    const uint32_t sB = sA + NSTG * A_ST;

    const int t    = threadIdx.x;
    const int warp = t >> 5;
    const int lane = t & 31;
    const int m0   = blockIdx.x * DBM;
    const int n0   = blockIdx.y * DBN;
    const int wm   = warp & 1;
    const int wn   = warp >> 1;
    const int g    = lane >> 2;
    const int tg   = lane & 3;

    const int mat = lane >> 3;
    const int sub = lane & 7;

    uint32_t aRowOff[4], aSw[4];
#pragma unroll
    for (int mi = 0; mi < 4; ++mi) {
        int r = wm * 64 + mi * 16 + (mat & 1) * 8 + sub;
        aRowOff[mi] = (uint32_t)(r * 128);
        aSw[mi]     = (uint32_t)(r & 7);
    }
    const uint32_t aMatK = (uint32_t)(mat >> 1);

    uint32_t bRowOff[4], bSw[4];
#pragma unroll
    for (int p = 0; p < 4; ++p) {
        int r = wn * 64 + (p * 2 + (mat >> 1)) * 8 + sub;
        bRowOff[p] = (uint32_t)(r * 128);
        bSw[p]     = (uint32_t)(r & 7);
    }
    const uint32_t bMatK = (uint32_t)(mat & 1);

    float acc[4][8][4];
#pragma unroll
    for (int mi = 0; mi < 4; ++mi)
#pragma unroll
        for (int ni = 0; ni < 8; ++ni)
#pragma unroll
            for (int r = 0; r < 4; ++r) acc[mi][ni][r] = 0.0f;

    auto load_chunk = [&](int c) {
        const int s  = c % NSTG;
        const int k0 = c * DBK;
#pragma unroll
        for (int i = 0; i < 8; ++i) {
            int id  = t + i * NTHR;
            int row = id >> 3;
            int kc  = id & 7;
            uint32_t sw = (uint32_t)(row * 128 + ((kc ^ (row & 7)) << 4));
            uint32_t dst = sA + s * A_ST + sw;
            const float* ga = A + (long)(m0 + row) * K + k0 + kc * 4;
            asm volatile("cp.async.cg.shared.global [%0], [%1], 16;" :: "r"(dst), "l"(ga));
        }
#pragma unroll
        for (int i = 0; i < 8; ++i) {
            int id  = t + i * NTHR;
            int row = id >> 3;
            int kc  = id & 7;
            uint32_t sw = (uint32_t)(row * 128 + ((kc ^ (row & 7)) << 4));
            uint32_t dst = sB + s * B_ST + sw;
            const float* gb = B + (long)(n0 + row) * K + k0 + kc * 4;
            asm volatile("cp.async.cg.shared.global [%0], [%1], 16;" :: "r"(dst), "l"(gb));
        }
        asm volatile("cp.async.commit_group;");
    };

    const int NCHUNK = K / DBK;   // 32
    load_chunk(0);
    load_chunk(1);

    for (int c = 0; c < NCHUNK; ++c) {
        const int buf = c % NSTG;
        asm volatile("cp.async.wait_group 1;");
        __syncthreads();

        if (c + 2 < NCHUNK) {
            load_chunk(c + 2);
        } else {
            asm volatile("cp.async.commit_group;");
        }

        const uint32_t Ab = sA + buf * A_ST;
        const uint32_t Bb = sB + buf * B_ST;

#pragma unroll
        for (int kk = 0; kk < 4; ++kk) {
            uint32_t a[4][4];
            uint32_t b[8][2];
            const uint32_t cA = (uint32_t)(kk * 2) + aMatK;
            const uint32_t cB = (uint32_t)(kk * 2) + bMatK;
#pragma unroll
            for (int mi = 0; mi < 4; ++mi) {
                uint32_t addr = Ab + aRowOff[mi] + (((cA ^ aSw[mi])) << 4);
                LDSM_X4(a[mi][0], a[mi][1], a[mi][2], a[mi][3], addr);
            }
#pragma unroll
            for (int p = 0; p < 4; ++p) {
                uint32_t addr = Bb + bRowOff[p] + (((cB ^ bSw[p])) << 4);
                uint32_t r0, r1, r2, r3;
                LDSM_X4(r0, r1, r2, r3, addr);
                b[2 * p][0] = r0;     b[2 * p][1] = r1;
                b[2 * p + 1][0] = r2; b[2 * p + 1][1] = r3;
            }
#pragma unroll
            for (int mi = 0; mi < 4; ++mi)
#pragma unroll
                for (int ni = 0; ni < 8; ++ni) {
                    asm volatile(
                        "mma.sync.aligned.m16n8k8.row.col.f32.tf32.tf32.f32 "
                        "{%0,%1,%2,%3}, {%4,%5,%6,%7}, {%8,%9}, {%0,%1,%2,%3};\n"
                        : "+f"(acc[mi][ni][0]), "+f"(acc[mi][ni][1]),
                          "+f"(acc[mi][ni][2]), "+f"(acc[mi][ni][3])
                        : "r"(a[mi][0]), "r"(a[mi][1]), "r"(a[mi][2]), "r"(a[mi][3]),
                          "r"(b[ni][0]), "r"(b[ni][1]));
                }
        }
    }

#pragma unroll
    for (int mi = 0; mi < 4; ++mi) {
        int rbase = m0 + wm * 64 + mi * 16 + g;
#pragma unroll
        for (int ni = 0; ni < 8; ++ni) {
            int cc = n0 + wn * 64 + ni * 8 + 2 * tg;
            float b0 = bias[cc], b1 = bias[cc + 1];
            float2 v0 = make_float2(acc[mi][ni][0] + b0, acc[mi][ni][1] + b1);
            float2 v1 = make_float2(acc[mi][ni][2] + b0, acc[mi][ni][3] + b1);
            *(float2*)(C + (long)rbase * N + cc)       = v0;
            *(float2*)(C + (long)(rbase + 8) * N + cc) = v1;
        }
    }
}

// ---------------- persistent RNN scan (restructured) ----------------
// 128 CTAs x 512 threads. CTA cb: col group jg = cb&31 (cols j0=jg*32),
// batch group bg = cb>>5 (batches b0=bg*8). Thread t: jj = t&31, kg = t>>5.
// W_hh fragment (64 floats for (j0+jj, kg*64..+64)) lives in REGISTERS.
// h (8 rows x 1024) staged to smem coalesced each step; read back as
// broadcast LDS (all lanes of a warp share kg -> same address).
// Barrier: 8 line-separated arrival counters (atom.add.release, 16 CTAs
// each); every CTA's thread 0 polls the 8-counter sum (monotonic gens).
#define SCAN_NB   128
#define SCAN_THR  512
#define HS_PAD    1032

__device__ __forceinline__ void scan_barrier(int cb, unsigned gen, int t) {
    __syncthreads();   // all global writes of this CTA issued
    if (t == 0) {
        unsigned dummy;
        asm volatile("atom.add.release.gpu.global.u32 %0, [%1], %2;"
                     : "=r"(dummy) : "l"(&g_arr[(cb & 7) * 32]), "r"(1u) : "memory");
        unsigned target = gen * (unsigned)SCAN_NB;
        unsigned sum;
        do {
            sum = 0;
#pragma unroll
            for (int i = 0; i < 8; ++i) {
                unsigned v;
                asm volatile("ld.acquire.gpu.global.u32 %0, [%1];"
                             : "=r"(v) : "l"(&g_arr[i * 32]) : "memory");
                sum += v;
            }
        } while (sum < target);
    }
    __syncthreads();   // propagate acquired visibility CTA-wide
}

__global__ __launch_bounds__(SCAN_THR)
void scan_kernel(const float* __restrict__ xin,
                 const float* __restrict__ h0,
                 const float* __restrict__ W_hh,
                 const float* __restrict__ b_hh,
                 const float* __restrict__ alpha,
                 float*       __restrict__ hs,
                 float*       __restrict__ hs32,
                 float*       __restrict__ hidden_f)
{
    extern __shared__ float sm[];
    float* hsh  = sm;                      // 8 * HS_PAD
    float* red  = sm + 8 * HS_PAD;         // 16 * 256
    float* alph = red + 16 * 256;          // 128

    const int t  = threadIdx.x;
    const int cb = blockIdx.x;
    const int jg = cb & 31;
    const int bg = cb >> 5;
    const int j0 = jg * 32;
    const int b0 = bg * 8;

    const int jj = t & 31;    // column within group
    const int kg = t >> 5;    // 0..15, K range [kg*64, kg*64+64)

    // preload alpha
    if (t < 128) alph[t] = alpha[t];

    // W fragment -> registers (64 floats as 32 packed f32x2)
    unsigned long long wf[32];
    {
        const float* wrow = W_hh + (long)(j0 + jj) * NHID + kg * 64;
#pragma unroll
        for (int q = 0; q < 16; ++q) {
            ulonglong2 w = *(const ulonglong2*)(wrow + q * 4);
            wf[2 * q]     = w.x;
            wf[2 * q + 1] = w.y;
        }
    }

    // reduce-phase constants (threads t < 256)
    const int rb  = t >> 5;         // batch 0..7  (t<256)
    const int rjj = t & 31;         // col within group
    const float bh = b_hh[j0 + rjj];

    __syncthreads();

    for (int s = 0; s < SEQ; ++s) {
        const float* hprev = (s == 0) ? (h0 + (long)b0 * NHID)
                                      : (hs + ((long)(s - 1) * BATCH + b0) * NHID);

        // stage 8 rows of h into smem (coalesced; 4 float4 per thread)
#pragma unroll
        for (int i = 0; i < 4; ++i) {
            int idx = t + i * SCAN_THR;        // 0..2047 float4
            int row = idx >> 8;                // 256 float4 per row
            int c4  = idx & 255;
            float4 v = *(const float4*)(hprev + (long)row * NHID + c4 * 4);
            *(float4*)&hsh[row * HS_PAD + c4 * 4] = v;
        }
        __syncthreads();

        // per-batch dot products over this thread's K range (W in regs,
        // h via broadcast LDS)
#pragma unroll
        for (int b = 0; b < 8; ++b) {
            const float* hb = &hsh[b * HS_PAD + kg * 64];
            unsigned long long a0 = 0ull, a1 = 0ull;
#pragma unroll
            for (int q = 0; q < 16; ++q) {
                ulonglong2 hq = *(const ulonglong2*)(hb + q * 4);
                FMA_X2(a0, hq.x, wf[2 * q]);
                FMA_X2(a1, hq.y, wf[2 * q + 1]);
            }
            float2 f0, f1;
            memcpy(&f0, &a0, 8);
            memcpy(&f1, &a1, 8);
            red[kg * 256 + b * 32 + jj] = (f0.x + f0.y) + (f1.x + f1.y);
        }
        __syncthreads();

        // final reduce over 16 kg groups + activation + writes (t < 256)
        if (t < 256) {
            float sum = 0.0f;
#pragma unroll
            for (int kk = 0; kk < 16; ++kk) sum += red[kk * 256 + rb * 32 + rjj];
            long idx = ((long)s * BATCH + b0 + rb) * NHID + j0 + rjj;
            float val = xin[idx] + sum + bh;
            float hnew = alph[s] * tanhf(val);
            hs[idx] = hnew;
            ((uint32_t*)hs32)[idx] = f2tf32(hnew);
            if (s == SEQ - 1) hidden_f[(long)(b0 + rb) * NHID + j0 + rjj] = hnew;
        }

        scan_barrier(cb, (unsigned)(s + 1), t);
    }
}

// ---------------- launch ----------------
extern "C" void kernel_launch(void* const* d_in, const int* in_sizes, int n_in,
                              void* d_out, int out_size)
{
    const int*   input  = (const int*)  d_in[0];
    const float* hidden = (const float*)d_in[1];
    const float* emb_W  = (const float*)d_in[2];
    const float* W_ih   = (const float*)d_in[3];
    const float* W_hh   = (const float*)d_in[4];
    const float* b_ih   = (const float*)d_in[5];
    const float* b_hh   = (const float*)d_in[6];
    const float* alpha  = (const float*)d_in[7];
    const float* dec_W  = (const float*)d_in[8];
    const float* dec_b  = (const float*)d_in[9];

    float* decoded  = (float*)d_out;                          // [S,B,NTOKEN]
    float* hidden_f = (float*)d_out + (long)MROWS * NTOKEN;   // [B,NHID]

    void *xin_p, *hs_p, *t32_p, *decw32_p, *wih32_p;
    cudaGetSymbolAddress(&xin_p,    g_xin);
    cudaGetSymbolAddress(&hs_p,     g_hs);
    cudaGetSymbolAddress(&t32_p,    g_t32buf);
    cudaGetSymbolAddress(&decw32_p, g_decW_t32);
    cudaGetSymbolAddress(&wih32_p,  g_wih_t32);
    float* xin     = (float*)xin_p;
    float* hs      = (float*)hs_p;
    float* t32     = (float*)t32_p;
    float* decw32  = (float*)decw32_p;
    float* wih32   = (float*)wih32_p;

    const int scan_smem = (8 * HS_PAD + 16 * 256 + 128) * (int)sizeof(float);
    cudaFuncSetAttribute(scan_kernel, cudaFuncAttributeMaxDynamicSharedMemorySize, scan_smem);
    cudaFuncSetAttribute(gemm_tf32_ldsm, cudaFuncAttributeMaxDynamicSharedMemorySize, DEC_SMEM);

    // 1) prep_a: dec_W -> tf32
    prep_a_kernel<<<2048, 256>>>(dec_W);

    // 2) prep_b: W_ih cvt + emb gather + counter reset
    prep_b_kernel<<<PREP_B_BLOCKS, 256>>>(W_ih, emb_W, input);

    // 3) xin = emb @ W_ih^T + b_ih on tensor cores [4096 x 1024]
    gemm_tf32_ldsm<<<dim3(MROWS / DBM, NHID / DBN), NTHR, DEC_SMEM>>>(
        t32, wih32, b_ih, xin, MROWS, NHID, NINP);

    // 4) recurrence — 4th launch: ncu target
    scan_kernel<<<SCAN_NB, SCAN_THR, scan_smem>>>(xin, hidden, W_hh, b_hh, alpha,
                                                  hs, t32, hidden_f);

    // 5) decoder: decoded = hs @ dec_W^T + dec_b  [4096 x 32000]
    gemm_tf32_ldsm<<<dim3(MROWS / DBM, NTOKEN / DBN), NTHR, DEC_SMEM>>>(
        t32, decw32, dec_b, decoded, MROWS, NTOKEN, NHID);
}

// round 12
// speedup vs baseline: 1.6043x; 1.1872x over previous
#include <cuda_runtime.h>
#include <cuda_bf16.h>
#include <math.h>
#include <stdint.h>
#include <string.h>

// Problem constants
#define SEQ    128
#define BATCH  32
#define NTOKEN 32000
#define NINP   1024
#define NHID   1024
#define MROWS  (SEQ * BATCH)          // 4096

// ---------------- scratch (no runtime allocation allowed) ----------------
__device__ float g_xin[MROWS * NHID];        // 16 MB
__device__ float g_hs [MROWS * NHID];        // 16 MB (fp32, scan-internal)
__device__ float g_t32buf[MROWS * NHID];     // 16 MB (tf32 bits: emb32 then hs32)
__device__ float g_decW_t32[NTOKEN * NHID];  // 131 MB (tf32 bits)
__device__ float g_wih_t32[NHID * NINP];     // 4 MB (tf32 bits)
__device__ unsigned g_arr[8 * 32];           // group counters, 128B apart

// ---------------- helpers ----------------
__device__ __forceinline__ uint32_t smem_u32(const void* p) {
    return (uint32_t)__cvta_generic_to_shared(p);
}
__device__ __forceinline__ uint32_t f2tf32(float x) {
    uint32_t r;
    asm("cvt.rna.tf32.f32 %0, %1;" : "=r"(r) : "f"(x));
    return r;
}

#define LDSM_X4(r0, r1, r2, r3, addr) \
    asm volatile("ldmatrix.sync.aligned.m8n8.x4.shared.b16 {%0,%1,%2,%3}, [%4];" \
        : "=r"(r0), "=r"(r1), "=r"(r2), "=r"(r3) : "r"(addr))

#define FMA_X2(acc, a, b) \
    asm volatile("fma.rn.f32x2 %0, %1, %2, %0;" : "+l"(acc) : "l"(a), "l"(b))

// =============== prep_a: dec_W -> tf32 (the big conversion) =============
__global__ __launch_bounds__(256)
void prep_a_kernel(const float* __restrict__ dec_W)
{
    const long n4 = (long)NTOKEN * NHID / 4;
    long i = (long)blockIdx.x * 256 + threadIdx.x;
    const long stride = (long)gridDim.x * 256;
    for (; i < n4; i += stride) {
        float4 v = ((const float4*)dec_W)[i];
        uint4 o = { f2tf32(v.x), f2tf32(v.y), f2tf32(v.z), f2tf32(v.w) };
        ((uint4*)g_decW_t32)[i] = o;
    }
}

// =============== prep_b: W_ih cvt + emb gather + counter reset =============
#define PREP_B_BLOCKS 192

__global__ __launch_bounds__(256)
void prep_b_kernel(const float* __restrict__ W_ih,
                   const float* __restrict__ emb_W,
                   const int*   __restrict__ input)
{
    const int bid = blockIdx.x;
    const int t   = threadIdx.x;
    if (bid == 0 && t < 256) g_arr[t] = 0u;

    if (bid < 64) {
        const long n4 = (long)NHID * NINP / 4;
        long i = (long)bid * 256 + t;
        const long stride = 64L * 256;
        for (; i < n4; i += stride) {
            float4 v = ((const float4*)W_ih)[i];
            uint4 o = { f2tf32(v.x), f2tf32(v.y), f2tf32(v.z), f2tf32(v.w) };
            ((uint4*)g_wih_t32)[i] = o;
        }
    } else {
        const long n4 = (long)MROWS * NINP / 4;
        long i = (long)(bid - 64) * 256 + t;
        const long stride = 128L * 256;
        for (; i < n4; i += stride) {
            int row = (int)(i >> 8);          // NINP/4 = 256 float4 per row
            int c4  = (int)(i & 255);
            int tok = input[row];
            float4 v = *(const float4*)(emb_W + (long)tok * NINP + c4 * 4);
            uint4 o = { f2tf32(v.x), f2tf32(v.y), f2tf32(v.z), f2tf32(v.w) };
            *(uint4*)(g_t32buf + (long)row * NINP + c4 * 4) = o;
        }
    }
}

// ============ tf32 mma.sync GEMM with ldmatrix fragments (R9 config) ========
#define DBM 128
#define DBN 128
#define DBK 32
#define NSTG 3
#define NTHR 128
#define A_ST (DBM * DBK * 4)   // 16 KB
#define B_ST (DBN * DBK * 4)   // 16 KB
#define DEC_SMEM (NSTG * (A_ST + B_ST))   // 96 KB

__global__ __launch_bounds__(NTHR, 2)
void gemm_tf32_ldsm(const float* __restrict__ A,
                    const float* __restrict__ B,
                    const float* __restrict__ bias,
                    float*       __restrict__ C,
                    int M, int N, int K)
{
    extern __shared__ __align__(1024) char smem[];
    const uint32_t sA = smem_u32(smem);
    const uint32_t sB = sA + NSTG * A_ST;

    const int t    = threadIdx.x;
    const int warp = t >> 5;
    const int lane = t & 31;
    const int m0   = blockIdx.x * DBM;
    const int n0   = blockIdx.y * DBN;
    const int wm   = warp & 1;
    const int wn   = warp >> 1;
    const int g    = lane >> 2;
    const int tg   = lane & 3;

    const int mat = lane >> 3;
    const int sub = lane & 7;

    uint32_t aRowOff[4], aSw[4];
#pragma unroll
    for (int mi = 0; mi < 4; ++mi) {
        int r = wm * 64 + mi * 16 + (mat & 1) * 8 + sub;
        aRowOff[mi] = (uint32_t)(r * 128);
        aSw[mi]     = (uint32_t)(r & 7);
    }
    const uint32_t aMatK = (uint32_t)(mat >> 1);

    uint32_t bRowOff[4], bSw[4];
#pragma unroll
    for (int p = 0; p < 4; ++p) {
        int r = wn * 64 + (p * 2 + (mat >> 1)) * 8 + sub;
        bRowOff[p] = (uint32_t)(r * 128);
        bSw[p]     = (uint32_t)(r & 7);
    }
    const uint32_t bMatK = (uint32_t)(mat & 1);

    float acc[4][8][4];
#pragma unroll
    for (int mi = 0; mi < 4; ++mi)
#pragma unroll
        for (int ni = 0; ni < 8; ++ni)
#pragma unroll
            for (int r = 0; r < 4; ++r) acc[mi][ni][r] = 0.0f;

    auto load_chunk = [&](int c) {
        const int s  = c % NSTG;
        const int k0 = c * DBK;
#pragma unroll
        for (int i = 0; i < 8; ++i) {
            int id  = t + i * NTHR;
            int row = id >> 3;
            int kc  = id & 7;
            uint32_t sw = (uint32_t)(row * 128 + ((kc ^ (row & 7)) << 4));
            uint32_t dst = sA + s * A_ST + sw;
            const float* ga = A + (long)(m0 + row) * K + k0 + kc * 4;
            asm volatile("cp.async.cg.shared.global [%0], [%1], 16;" :: "r"(dst), "l"(ga));
        }
#pragma unroll
        for (int i = 0; i < 8; ++i) {
            int id  = t + i * NTHR;
            int row = id >> 3;
            int kc  = id & 7;
            uint32_t sw = (uint32_t)(row * 128 + ((kc ^ (row & 7)) << 4));
            uint32_t dst = sB + s * B_ST + sw;
            const float* gb = B + (long)(n0 + row) * K + k0 + kc * 4;
            asm volatile("cp.async.cg.shared.global [%0], [%1], 16;" :: "r"(dst), "l"(gb));
        }
        asm volatile("cp.async.commit_group;");
    };

    const int NCHUNK = K / DBK;   // 32
    load_chunk(0);
    load_chunk(1);

    for (int c = 0; c < NCHUNK; ++c) {
        const int buf = c % NSTG;
        asm volatile("cp.async.wait_group 1;");
        __syncthreads();

        if (c + 2 < NCHUNK) {
            load_chunk(c + 2);
        } else {
            asm volatile("cp.async.commit_group;");
        }

        const uint32_t Ab = sA + buf * A_ST;
        const uint32_t Bb = sB + buf * B_ST;

#pragma unroll
        for (int kk = 0; kk < 4; ++kk) {
            uint32_t a[4][4];
            uint32_t b[8][2];
            const uint32_t cA = (uint32_t)(kk * 2) + aMatK;
            const uint32_t cB = (uint32_t)(kk * 2) + bMatK;
#pragma unroll
            for (int mi = 0; mi < 4; ++mi) {
                uint32_t addr = Ab + aRowOff[mi] + (((cA ^ aSw[mi])) << 4);
                LDSM_X4(a[mi][0], a[mi][1], a[mi][2], a[mi][3], addr);
            }
#pragma unroll
            for (int p = 0; p < 4; ++p) {
                uint32_t addr = Bb + bRowOff[p] + (((cB ^ bSw[p])) << 4);
                uint32_t r0, r1, r2, r3;
                LDSM_X4(r0, r1, r2, r3, addr);
                b[2 * p][0] = r0;     b[2 * p][1] = r1;
                b[2 * p + 1][0] = r2; b[2 * p + 1][1] = r3;
            }
#pragma unroll
            for (int mi = 0; mi < 4; ++mi)
#pragma unroll
                for (int ni = 0; ni < 8; ++ni) {
                    asm volatile(
                        "mma.sync.aligned.m16n8k8.row.col.f32.tf32.tf32.f32 "
                        "{%0,%1,%2,%3}, {%4,%5,%6,%7}, {%8,%9}, {%0,%1,%2,%3};\n"
                        : "+f"(acc[mi][ni][0]), "+f"(acc[mi][ni][1]),
                          "+f"(acc[mi][ni][2]), "+f"(acc[mi][ni][3])
                        : "r"(a[mi][0]), "r"(a[mi][1]), "r"(a[mi][2]), "r"(a[mi][3]),
                          "r"(b[ni][0]), "r"(b[ni][1]));
                }
        }
    }

#pragma unroll
    for (int mi = 0; mi < 4; ++mi) {
        int rbase = m0 + wm * 64 + mi * 16 + g;
#pragma unroll
        for (int ni = 0; ni < 8; ++ni) {
            int cc = n0 + wn * 64 + ni * 8 + 2 * tg;
            float b0 = bias[cc], b1 = bias[cc + 1];
            float2 v0 = make_float2(acc[mi][ni][0] + b0, acc[mi][ni][1] + b1);
            float2 v1 = make_float2(acc[mi][ni][2] + b0, acc[mi][ni][3] + b1);
            *(float2*)(C + (long)rbase * N + cc)       = v0;
            *(float2*)(C + (long)(rbase + 8) * N + cc) = v1;
        }
    }
}

// ---------------- persistent RNN scan: 4 independent sync groups -----------
// 256 CTAs x 256 threads, 2 CTAs/SM (all 256 co-resident of 296 slots).
// Group bg = cb>>6 owns batches [bg*8, bg*8+8) — batches are INDEPENDENT in
// the recurrence, so each group syncs only among its own 64 CTAs. Same-SM
// wave pairs (cb, cb+148) differ in bg (148>>6 = 2), so the co-resident CTA
// computes while this one waits at its group barrier.
// CTA covers cols [jg*16, jg*16+16), jg = cb&63. Thread = (jj = t&15,
// kg = t>>4): W fragment (64 floats) in registers; h staged coalesced to
// smem; broadcast LDS reads.
#define SCAN_NB   256
#define SCAN_THR  256
#define SCAN_GRP  64          // CTAs per group
#define HS_PAD    1032

__device__ __forceinline__ void group_barrier(int bg, unsigned gen, int t) {
    __syncthreads();   // all global writes of this CTA issued
    if (t == 0) {
        asm volatile("red.release.gpu.global.add.u32 [%0], %1;"
                     :: "l"(&g_arr[bg * 32]), "r"(1u) : "memory");
        unsigned target = gen * (unsigned)SCAN_GRP;
        unsigned v;
        do {
            asm volatile("ld.acquire.gpu.global.u32 %0, [%1];"
                         : "=r"(v) : "l"(&g_arr[bg * 32]) : "memory");
        } while (v < target);
    }
    __syncthreads();   // propagate acquired visibility CTA-wide
}

__global__ __launch_bounds__(SCAN_THR, 2)
void scan_kernel(const float* __restrict__ xin,
                 const float* __restrict__ h0,
                 const float* __restrict__ W_hh,
                 const float* __restrict__ b_hh,
                 const float* __restrict__ alpha,
                 float*       __restrict__ hs,
                 float*       __restrict__ hs32,
                 float*       __restrict__ hidden_f)
{
    extern __shared__ float sm[];
    float* hsh  = sm;                      // 8 * HS_PAD
    float* red  = sm + 8 * HS_PAD;         // 16 * 8 * 16 = 2048
    float* alph = red + 2048;              // 128

    const int t  = threadIdx.x;
    const int cb = blockIdx.x;
    const int bg = cb >> 6;        // group 0..3 (8 batches each)
    const int jg = cb & 63;        // col group 0..63 (16 cols each)
    const int j0 = jg * 16;
    const int b0 = bg * 8;

    const int jj = t & 15;    // column within group
    const int kg = t >> 4;    // 0..15, K range [kg*64, kg*64+64)

    if (t < 128) alph[t] = alpha[t];

    // W fragment -> registers (64 floats as 32 packed f32x2)
    unsigned long long wf[32];
    {
        const float* wrow = W_hh + (long)(j0 + jj) * NHID + kg * 64;
#pragma unroll
        for (int q = 0; q < 16; ++q) {
            ulonglong2 w = *(const ulonglong2*)(wrow + q * 4);
            wf[2 * q]     = w.x;
            wf[2 * q + 1] = w.y;
        }
    }

    // reduce-phase constants (threads t < 128): rb = batch, rjj = col
    const int rb  = t >> 4;
    const int rjj = t & 15;
    const float bh = b_hh[j0 + rjj];

    __syncthreads();

    for (int s = 0; s < SEQ; ++s) {
        const float* hprev = (s == 0) ? (h0 + (long)b0 * NHID)
                                      : (hs + ((long)(s - 1) * BATCH + b0) * NHID);

        // prefetch xin early (independent of h; hides DRAM latency)
        float xv = 0.0f;
        long widx = 0;
        if (t < 128) {
            widx = ((long)s * BATCH + b0 + rb) * NHID + j0 + rjj;
            xv = xin[widx];
        }

        // stage 8 rows of h into smem (coalesced; 8 float4 per thread)
#pragma unroll
        for (int i = 0; i < 8; ++i) {
            int idx = t + i * SCAN_THR;        // 0..2047 float4
            int row = idx >> 8;                // 256 float4 per row
            int c4  = idx & 255;
            float4 v = *(const float4*)(hprev + (long)row * NHID + c4 * 4);
            *(float4*)&hsh[row * HS_PAD + c4 * 4] = v;
        }
        __syncthreads();

        // per-batch dot products over this thread's K range
#pragma unroll
        for (int b = 0; b < 8; ++b) {
            const float* hb = &hsh[b * HS_PAD + kg * 64];
            unsigned long long a0 = 0ull, a1 = 0ull;
#pragma unroll
            for (int q = 0; q < 16; ++q) {
                ulonglong2 hq = *(const ulonglong2*)(hb + q * 4);
                FMA_X2(a0, hq.x, wf[2 * q]);
                FMA_X2(a1, hq.y, wf[2 * q + 1]);
            }
            float2 f0, f1;
            memcpy(&f0, &a0, 8);
            memcpy(&f1, &a1, 8);
            red[(kg * 8 + b) * 16 + jj] = (f0.x + f0.y) + (f1.x + f1.y);
        }
        __syncthreads();

        // final reduce over 16 kg groups + activation + writes (t < 128)
        if (t < 128) {
            float sum = 0.0f;
#pragma unroll
            for (int kk = 0; kk < 16; ++kk) sum += red[(kk * 8 + rb) * 16 + rjj];
            float val = xv + sum + bh;
            float hnew = alph[s] * tanhf(val);
            hs[widx] = hnew;
            ((uint32_t*)hs32)[widx] = f2tf32(hnew);
            if (s == SEQ - 1) hidden_f[(long)(b0 + rb) * NHID + j0 + rjj] = hnew;
        }

        if (s < SEQ - 1) group_barrier(bg, (unsigned)(s + 1), t);
    }
}

// ---------------- launch ----------------
extern "C" void kernel_launch(void* const* d_in, const int* in_sizes, int n_in,
                              void* d_out, int out_size)
{
    const int*   input  = (const int*)  d_in[0];
    const float* hidden = (const float*)d_in[1];
    const float* emb_W  = (const float*)d_in[2];
    const float* W_ih   = (const float*)d_in[3];
    const float* W_hh   = (const float*)d_in[4];
    const float* b_ih   = (const float*)d_in[5];
    const float* b_hh   = (const float*)d_in[6];
    const float* alpha  = (const float*)d_in[7];
    const float* dec_W  = (const float*)d_in[8];
    const float* dec_b  = (const float*)d_in[9];

    float* decoded  = (float*)d_out;                          // [S,B,NTOKEN]
    float* hidden_f = (float*)d_out + (long)MROWS * NTOKEN;   // [B,NHID]

    void *xin_p, *hs_p, *t32_p, *decw32_p, *wih32_p;
    cudaGetSymbolAddress(&xin_p,    g_xin);
    cudaGetSymbolAddress(&hs_p,     g_hs);
    cudaGetSymbolAddress(&t32_p,    g_t32buf);
    cudaGetSymbolAddress(&decw32_p, g_decW_t32);
    cudaGetSymbolAddress(&wih32_p,  g_wih_t32);
    float* xin     = (float*)xin_p;
    float* hs      = (float*)hs_p;
    float* t32     = (float*)t32_p;
    float* decw32  = (float*)decw32_p;
    float* wih32   = (float*)wih32_p;

    const int scan_smem = (8 * HS_PAD + 2048 + 128) * (int)sizeof(float);
    cudaFuncSetAttribute(scan_kernel, cudaFuncAttributeMaxDynamicSharedMemorySize, scan_smem);
    cudaFuncSetAttribute(gemm_tf32_ldsm, cudaFuncAttributeMaxDynamicSharedMemorySize, DEC_SMEM);

    // 1) prep_a: dec_W -> tf32
    prep_a_kernel<<<2048, 256>>>(dec_W);

    // 2) prep_b: W_ih cvt + emb gather + counter reset
    prep_b_kernel<<<PREP_B_BLOCKS, 256>>>(W_ih, emb_W, input);

    // 3) xin = emb @ W_ih^T + b_ih on tensor cores [4096 x 1024]
    gemm_tf32_ldsm<<<dim3(MROWS / DBM, NHID / DBN), NTHR, DEC_SMEM>>>(
        t32, wih32, b_ih, xin, MROWS, NHID, NINP);

    // 4) recurrence — 4th launch: ncu target
    scan_kernel<<<SCAN_NB, SCAN_THR, scan_smem>>>(xin, hidden, W_hh, b_hh, alpha,
                                                  hs, t32, hidden_f);

    // 5) decoder: decoded = hs @ dec_W^T + dec_b  [4096 x 32000]
    gemm_tf32_ldsm<<<dim3(MROWS / DBM, NTOKEN / DBN), NTHR, DEC_SMEM>>>(
        t32, decw32, dec_b, decoded, MROWS, NTOKEN, NHID);
}

// round 13
// speedup vs baseline: 2.3816x; 1.4845x over previous
#include <cuda_runtime.h>
#include <cuda_bf16.h>
#include <cuda_fp16.h>
#include <math.h>
#include <stdint.h>
#include <string.h>

// Problem constants
#define SEQ    128
#define BATCH  32
#define NTOKEN 32000
#define NINP   1024
#define NHID   1024
#define MROWS  (SEQ * BATCH)          // 4096

// ---------------- scratch (no runtime allocation allowed) ----------------
__device__ float  g_xin[MROWS * NHID];        // 16 MB
__device__ float  g_hs [MROWS * NHID];        // 16 MB (fp32, scan-internal)
__device__ __half g_h16buf[MROWS * NHID];     // 8 MB (fp16: emb16 then hs16)
__device__ __half g_decW_h[NTOKEN * NHID];    // 64 MB (fp16)
__device__ __half g_wih_h[NHID * NINP];       // 2 MB (fp16)
__device__ unsigned g_arr[8 * 32];            // group counters, 128B apart

// ---------------- helpers ----------------
__device__ __forceinline__ uint32_t smem_u32(const void* p) {
    return (uint32_t)__cvta_generic_to_shared(p);
}

#define LDSM_X4(r0, r1, r2, r3, addr) \
    asm volatile("ldmatrix.sync.aligned.m8n8.x4.shared.b16 {%0,%1,%2,%3}, [%4];" \
        : "=r"(r0), "=r"(r1), "=r"(r2), "=r"(r3) : "r"(addr))

#define FMA_X2(acc, a, b) \
    asm volatile("fma.rn.f32x2 %0, %1, %2, %0;" : "+l"(acc) : "l"(a), "l"(b))

// =============== prep_a: dec_W -> fp16 (the big conversion) =============
__global__ __launch_bounds__(256)
void prep_a_kernel(const float* __restrict__ dec_W)
{
    const long n4 = (long)NTOKEN * NHID / 4;
    long i = (long)blockIdx.x * 256 + threadIdx.x;
    const long stride = (long)gridDim.x * 256;
    for (; i < n4; i += stride) {
        float4 v = ((const float4*)dec_W)[i];
        __half2 h0 = __floats2half2_rn(v.x, v.y);
        __half2 h1 = __floats2half2_rn(v.z, v.w);
        uint2 o = { *(uint32_t*)&h0, *(uint32_t*)&h1 };
        ((uint2*)g_decW_h)[i] = o;
    }
}

// =============== prep_b: W_ih cvt + emb gather + counter reset =============
#define PREP_B_BLOCKS 192

__global__ __launch_bounds__(256)
void prep_b_kernel(const float* __restrict__ W_ih,
                   const float* __restrict__ emb_W,
                   const int*   __restrict__ input)
{
    const int bid = blockIdx.x;
    const int t   = threadIdx.x;
    if (bid == 0 && t < 256) g_arr[t] = 0u;

    if (bid < 64) {
        const long n4 = (long)NHID * NINP / 4;
        long i = (long)bid * 256 + t;
        const long stride = 64L * 256;
        for (; i < n4; i += stride) {
            float4 v = ((const float4*)W_ih)[i];
            __half2 h0 = __floats2half2_rn(v.x, v.y);
            __half2 h1 = __floats2half2_rn(v.z, v.w);
            uint2 o = { *(uint32_t*)&h0, *(uint32_t*)&h1 };
            ((uint2*)g_wih_h)[i] = o;
        }
    } else {
        const long n4 = (long)MROWS * NINP / 4;
        long i = (long)(bid - 64) * 256 + t;
        const long stride = 128L * 256;
        for (; i < n4; i += stride) {
            int row = (int)(i >> 8);          // NINP/4 = 256 float4 per row
            int c4  = (int)(i & 255);
            int tok = input[row];
            float4 v = *(const float4*)(emb_W + (long)tok * NINP + c4 * 4);
            __half2 h0 = __floats2half2_rn(v.x, v.y);
            __half2 h1 = __floats2half2_rn(v.z, v.w);
            uint2 o = { *(uint32_t*)&h0, *(uint32_t*)&h1 };
            *(uint2*)(g_h16buf + (long)row * NINP + c4 * 4) = o;
        }
    }
}

// ============ fp16 mma.sync GEMM with ldmatrix fragments ============
// C[M,N] = A[M,K]*B[N,K]^T + bias, A/B fp16, acc fp32.
// CTA tile 128x128, BK=64 halves (128B/row), 4 warps (64x64 each),
// 128 threads, 2 CTAs/SM. Swizzled 128B smem rows (16B chunk kc ^ row&7).
// 3 buffers, 2 cp.async groups in flight, ONE __syncthreads per chunk.
// mma.m16n8k16: kk iter consumes 2 chunks (k=16 halves).
#define DBM 128
#define DBN 128
#define DBK 64                   // halves per tile row = 128 bytes
#define NSTG 3
#define NTHR 128
#define A_ST (DBM * 128)         // 16 KB
#define B_ST (DBN * 128)         // 16 KB
#define DEC_SMEM (NSTG * (A_ST + B_ST))   // 96 KB

__global__ __launch_bounds__(NTHR, 2)
void gemm_f16_ldsm(const __half* __restrict__ A,
                   const __half* __restrict__ B,
                   const float*  __restrict__ bias,
                   float*        __restrict__ C,
                   int M, int N, int K)
{
    extern __shared__ __align__(1024) char smem[];
    const uint32_t sA = smem_u32(smem);
    const uint32_t sB = sA + NSTG * A_ST;

    const int t    = threadIdx.x;
    const int warp = t >> 5;
    const int lane = t & 31;
    const int m0   = blockIdx.x * DBM;
    const int n0   = blockIdx.y * DBN;
    const int wm   = warp & 1;
    const int wn   = warp >> 1;
    const int g    = lane >> 2;
    const int tg   = lane & 3;

    const int mat = lane >> 3;
    const int sub = lane & 7;

    // A fragments: mat0=(rows+0, chunk even), mat1=(rows+8, even),
    //              mat2=(rows+0, odd), mat3=(rows+8, odd)  -> a0..a3
    uint32_t aRowOff[4], aSw[4];
#pragma unroll
    for (int mi = 0; mi < 4; ++mi) {
        int r = wm * 64 + mi * 16 + (mat & 1) * 8 + sub;
        aRowOff[mi] = (uint32_t)(r * 128);
        aSw[mi]     = (uint32_t)(r & 7);
    }
    const uint32_t aMatK = (uint32_t)(mat >> 1);

    // B fragments: mat0=(n-group 2p, even)->b0, mat1=(2p, odd)->b1,
    //              mat2=(2p+1, even), mat3=(2p+1, odd)
    uint32_t bRowOff[4], bSw[4];
#pragma unroll
    for (int p = 0; p < 4; ++p) {
        int r = wn * 64 + (p * 2 + (mat >> 1)) * 8 + sub;
        bRowOff[p] = (uint32_t)(r * 128);
        bSw[p]     = (uint32_t)(r & 7);
    }
    const uint32_t bMatK = (uint32_t)(mat & 1);

    float acc[4][8][4];
#pragma unroll
    for (int mi = 0; mi < 4; ++mi)
#pragma unroll
        for (int ni = 0; ni < 8; ++ni)
#pragma unroll
            for (int r = 0; r < 4; ++r) acc[mi][ni][r] = 0.0f;

    auto load_chunk = [&](int c) {
        const int s  = c % NSTG;
        const int k0 = c * DBK;
#pragma unroll
        for (int i = 0; i < 8; ++i) {
            int id  = t + i * NTHR;
            int row = id >> 3;
            int kc  = id & 7;
            uint32_t sw = (uint32_t)(row * 128 + ((kc ^ (row & 7)) << 4));
            uint32_t dst = sA + s * A_ST + sw;
            const __half* ga = A + (long)(m0 + row) * K + k0 + kc * 8;
            asm volatile("cp.async.cg.shared.global [%0], [%1], 16;" :: "r"(dst), "l"(ga));
        }
#pragma unroll
        for (int i = 0; i < 8; ++i) {
            int id  = t + i * NTHR;
            int row = id >> 3;
            int kc  = id & 7;
            uint32_t sw = (uint32_t)(row * 128 + ((kc ^ (row & 7)) << 4));
            uint32_t dst = sB + s * B_ST + sw;
            const __half* gb = B + (long)(n0 + row) * K + k0 + kc * 8;
            asm volatile("cp.async.cg.shared.global [%0], [%1], 16;" :: "r"(dst), "l"(gb));
        }
        asm volatile("cp.async.commit_group;");
    };

    const int NCHUNK = K / DBK;   // 16
    load_chunk(0);
    load_chunk(1);

    for (int c = 0; c < NCHUNK; ++c) {
        const int buf = c % NSTG;
        asm volatile("cp.async.wait_group 1;");
        __syncthreads();

        if (c + 2 < NCHUNK) {
            load_chunk(c + 2);
        } else {
            asm volatile("cp.async.commit_group;");
        }

        const uint32_t Ab = sA + buf * A_ST;
        const uint32_t Bb = sB + buf * B_ST;

#pragma unroll
        for (int kk = 0; kk < 4; ++kk) {     // k16 per iter
            uint32_t a[4][4];
            uint32_t b[8][2];
            const uint32_t cA = (uint32_t)(kk * 2) + aMatK;
            const uint32_t cB = (uint32_t)(kk * 2) + bMatK;
#pragma unroll
            for (int mi = 0; mi < 4; ++mi) {
                uint32_t addr = Ab + aRowOff[mi] + (((cA ^ aSw[mi])) << 4);
                LDSM_X4(a[mi][0], a[mi][1], a[mi][2], a[mi][3], addr);
            }
#pragma unroll
            for (int p = 0; p < 4; ++p) {
                uint32_t addr = Bb + bRowOff[p] + (((cB ^ bSw[p])) << 4);
                uint32_t r0, r1, r2, r3;
                LDSM_X4(r0, r1, r2, r3, addr);
                b[2 * p][0] = r0;     b[2 * p][1] = r1;
                b[2 * p + 1][0] = r2; b[2 * p + 1][1] = r3;
            }
#pragma unroll
            for (int mi = 0; mi < 4; ++mi)
#pragma unroll
                for (int ni = 0; ni < 8; ++ni) {
                    asm volatile(
                        "mma.sync.aligned.m16n8k16.row.col.f32.f16.f16.f32 "
                        "{%0,%1,%2,%3}, {%4,%5,%6,%7}, {%8,%9}, {%0,%1,%2,%3};\n"
                        : "+f"(acc[mi][ni][0]), "+f"(acc[mi][ni][1]),
                          "+f"(acc[mi][ni][2]), "+f"(acc[mi][ni][3])
                        : "r"(a[mi][0]), "r"(a[mi][1]), "r"(a[mi][2]), "r"(a[mi][3]),
                          "r"(b[ni][0]), "r"(b[ni][1]));
                }
        }
    }

    // ---- epilogue: add bias, store ----
#pragma unroll
    for (int mi = 0; mi < 4; ++mi) {
        int rbase = m0 + wm * 64 + mi * 16 + g;
#pragma unroll
        for (int ni = 0; ni < 8; ++ni) {
            int cc = n0 + wn * 64 + ni * 8 + 2 * tg;
            float b0 = bias[cc], b1 = bias[cc + 1];
            float2 v0 = make_float2(acc[mi][ni][0] + b0, acc[mi][ni][1] + b1);
            float2 v1 = make_float2(acc[mi][ni][2] + b0, acc[mi][ni][3] + b1);
            *(float2*)(C + (long)rbase * N + cc)       = v0;
            *(float2*)(C + (long)(rbase + 8) * N + cc) = v1;
        }
    }
}

// ---------------- persistent RNN scan: 4 independent sync groups -----------
// (unchanged from R12 except hs16 output is fp16)
#define SCAN_NB   256
#define SCAN_THR  256
#define SCAN_GRP  64
#define HS_PAD    1032

__device__ __forceinline__ void group_barrier(int bg, unsigned gen, int t) {
    __syncthreads();
    if (t == 0) {
        asm volatile("red.release.gpu.global.add.u32 [%0], %1;"
                     :: "l"(&g_arr[bg * 32]), "r"(1u) : "memory");
        unsigned target = gen * (unsigned)SCAN_GRP;
        unsigned v;
        do {
            asm volatile("ld.acquire.gpu.global.u32 %0, [%1];"
                         : "=r"(v) : "l"(&g_arr[bg * 32]) : "memory");
        } while (v < target);
    }
    __syncthreads();
}

__global__ __launch_bounds__(SCAN_THR, 2)
void scan_kernel(const float* __restrict__ xin,
                 const float* __restrict__ h0,
                 const float* __restrict__ W_hh,
                 const float* __restrict__ b_hh,
                 const float* __restrict__ alpha,
                 float*       __restrict__ hs,
                 __half*      __restrict__ hs16,
                 float*       __restrict__ hidden_f)
{
    extern __shared__ float sm[];
    float* hsh  = sm;                      // 8 * HS_PAD
    float* red  = sm + 8 * HS_PAD;         // 2048
    float* alph = red + 2048;              // 128

    const int t  = threadIdx.x;
    const int cb = blockIdx.x;
    const int bg = cb >> 6;
    const int jg = cb & 63;
    const int j0 = jg * 16;
    const int b0 = bg * 8;

    const int jj = t & 15;
    const int kg = t >> 4;

    if (t < 128) alph[t] = alpha[t];

    unsigned long long wf[32];
    {
        const float* wrow = W_hh + (long)(j0 + jj) * NHID + kg * 64;
#pragma unroll
        for (int q = 0; q < 16; ++q) {
            ulonglong2 w = *(const ulonglong2*)(wrow + q * 4);
            wf[2 * q]     = w.x;
            wf[2 * q + 1] = w.y;
        }
    }

    const int rb  = t >> 4;
    const int rjj = t & 15;
    const float bh = b_hh[j0 + rjj];

    __syncthreads();

    for (int s = 0; s < SEQ; ++s) {
        const float* hprev = (s == 0) ? (h0 + (long)b0 * NHID)
                                      : (hs + ((long)(s - 1) * BATCH + b0) * NHID);

        float xv = 0.0f;
        long widx = 0;
        if (t < 128) {
            widx = ((long)s * BATCH + b0 + rb) * NHID + j0 + rjj;
            xv = xin[widx];
        }

#pragma unroll
        for (int i = 0; i < 8; ++i) {
            int idx = t + i * SCAN_THR;
            int row = idx >> 8;
            int c4  = idx & 255;
            float4 v = *(const float4*)(hprev + (long)row * NHID + c4 * 4);
            *(float4*)&hsh[row * HS_PAD + c4 * 4] = v;
        }
        __syncthreads();

#pragma unroll
        for (int b = 0; b < 8; ++b) {
            const float* hb = &hsh[b * HS_PAD + kg * 64];
            unsigned long long a0 = 0ull, a1 = 0ull;
#pragma unroll
            for (int q = 0; q < 16; ++q) {
                ulonglong2 hq = *(const ulonglong2*)(hb + q * 4);
                FMA_X2(a0, hq.x, wf[2 * q]);
                FMA_X2(a1, hq.y, wf[2 * q + 1]);
            }
            float2 f0, f1;
            memcpy(&f0, &a0, 8);
            memcpy(&f1, &a1, 8);
            red[(kg * 8 + b) * 16 + jj] = (f0.x + f0.y) + (f1.x + f1.y);
        }
        __syncthreads();

        if (t < 128) {
            float sum = 0.0f;
#pragma unroll
            for (int kk = 0; kk < 16; ++kk) sum += red[(kk * 8 + rb) * 16 + rjj];
            float val = xv + sum + bh;
            float hnew = alph[s] * tanhf(val);
            hs[widx] = hnew;
            hs16[widx] = __float2half_rn(hnew);
            if (s == SEQ - 1) hidden_f[(long)(b0 + rb) * NHID + j0 + rjj] = hnew;
        }

        if (s < SEQ - 1) group_barrier(bg, (unsigned)(s + 1), t);
    }
}

// ---------------- launch ----------------
extern "C" void kernel_launch(void* const* d_in, const int* in_sizes, int n_in,
                              void* d_out, int out_size)
{
    const int*   input  = (const int*)  d_in[0];
    const float* hidden = (const float*)d_in[1];
    const float* emb_W  = (const float*)d_in[2];
    const float* W_ih   = (const float*)d_in[3];
    const float* W_hh   = (const float*)d_in[4];
    const float* b_ih   = (const float*)d_in[5];
    const float* b_hh   = (const float*)d_in[6];
    const float* alpha  = (const float*)d_in[7];
    const float* dec_W  = (const float*)d_in[8];
    const float* dec_b  = (const float*)d_in[9];

    float* decoded  = (float*)d_out;                          // [S,B,NTOKEN]
    float* hidden_f = (float*)d_out + (long)MROWS * NTOKEN;   // [B,NHID]

    void *xin_p, *hs_p, *h16_p, *decwh_p, *wihh_p;
    cudaGetSymbolAddress(&xin_p,   g_xin);
    cudaGetSymbolAddress(&hs_p,    g_hs);
    cudaGetSymbolAddress(&h16_p,   g_h16buf);
    cudaGetSymbolAddress(&decwh_p, g_decW_h);
    cudaGetSymbolAddress(&wihh_p,  g_wih_h);
    float*  xin    = (float*)xin_p;
    float*  hs     = (float*)hs_p;
    __half* h16    = (__half*)h16_p;    // emb16 first, hs16 later
    __half* decwh  = (__half*)decwh_p;
    __half* wihh   = (__half*)wihh_p;

    const int scan_smem = (8 * HS_PAD + 2048 + 128) * (int)sizeof(float);
    cudaFuncSetAttribute(scan_kernel, cudaFuncAttributeMaxDynamicSharedMemorySize, scan_smem);
    cudaFuncSetAttribute(gemm_f16_ldsm, cudaFuncAttributeMaxDynamicSharedMemorySize, DEC_SMEM);

    // 1) prep_a: dec_W -> fp16
    prep_a_kernel<<<2048, 256>>>(dec_W);

    // 2) prep_b: W_ih cvt + emb gather (fp16) + counter reset
    prep_b_kernel<<<PREP_B_BLOCKS, 256>>>(W_ih, emb_W, input);

    // 3) xin = emb @ W_ih^T + b_ih on fp16 tensor cores [4096 x 1024]
    gemm_f16_ldsm<<<dim3(MROWS / DBM, NHID / DBN), NTHR, DEC_SMEM>>>(
        h16, wihh, b_ih, xin, MROWS, NHID, NINP);

    // 4) recurrence — 4th launch: ncu target
    scan_kernel<<<SCAN_NB, SCAN_THR, scan_smem>>>(xin, hidden, W_hh, b_hh, alpha,
                                                  hs, h16, hidden_f);

    // 5) decoder: decoded = hs @ dec_W^T + dec_b  [4096 x 32000]
    gemm_f16_ldsm<<<dim3(MROWS / DBM, NTOKEN / DBN), NTHR, DEC_SMEM>>>(
        h16, decwh, dec_b, decoded, MROWS, NTOKEN, NHID);
}